// round 4
// baseline (speedup 1.0000x reference)
#include <cuda_runtime.h>
#include <math.h>

#define BB 32
#define MM 1024
#define NN 1024
#define SS 16     // n-split factor
#define TN 64     // n per block tile (SS*TN = NN)

typedef unsigned long long u64;

// ---------------- scratch (no allocations allowed) ----------------
__device__ float g_c[BB * MM];
__device__ float g_part[SS][BB * MM];       // partial sqrt-sums per n-chunk
__device__ float g_dish[BB * MM];           // sum over all n (not yet /N)
__device__ float g_lpart[256];              // per-combine-block loss partials
__device__ float g_amaxv[BB * 2];           // per-(b,h) argmax partials
__device__ int   g_amaxi[BB * 2];
__device__ int   g_which[BB];
__device__ float g_Rbest[BB][12];           // R row-major (9) + t_best (3)

// ---------------- f32x2 helpers (sm_103a packed fp32) ----------------
__device__ __forceinline__ u64 pack2(float a, float b) {
    u64 r; asm("mov.b64 %0, {%1,%2};" : "=l"(r) : "f"(a), "f"(b)); return r;
}
__device__ __forceinline__ void unpack2(u64 v, float& a, float& b) {
    asm("mov.b64 {%0,%1}, %2;" : "=f"(a), "=f"(b) : "l"(v));
}
__device__ __forceinline__ u64 fma2(u64 a, u64 b, u64 c) {
    u64 r; asm("fma.rn.f32x2 %0, %1, %2, %3;" : "=l"(r) : "l"(a), "l"(b), "l"(c)); return r;
}
__device__ __forceinline__ u64 mul2(u64 a, u64 b) {
    u64 r; asm("mul.rn.f32x2 %0, %1, %2;" : "=l"(r) : "l"(a), "l"(b)); return r;
}
__device__ __forceinline__ float sqrt_approx(float x) {
    float r; asm("sqrt.approx.f32 %0, %1;" : "=f"(r) : "f"(x)); return r;
}

// quat (xyzw) + t -> 12 floats: R row-major then t
__device__ __forceinline__ void quat_to_Rt(float qx, float qy, float qz, float qw,
                                           float t0, float t1, float t2, float* o) {
    float nrm = sqrtf(qx * qx + qy * qy + qz * qz + qw * qw);
    float inv = __fdividef(1.0f, nrm + 1e-8f);
    qx *= inv; qy *= inv; qz *= inv; qw *= inv;
    o[0] = 1.0f - 2.0f * (qy * qy + qz * qz);
    o[1] = 2.0f * (qx * qy - qz * qw);
    o[2] = 2.0f * (qx * qz + qy * qw);
    o[3] = 2.0f * (qx * qy + qz * qw);
    o[4] = 1.0f - 2.0f * (qx * qx + qz * qz);
    o[5] = 2.0f * (qy * qz - qx * qw);
    o[6] = 2.0f * (qx * qz - qy * qw);
    o[7] = 2.0f * (qy * qz + qx * qw);
    o[8] = 1.0f - 2.0f * (qx * qx + qy * qy);
    o[9] = t0; o[10] = t1; o[11] = t2;
}

// ---------------- K1: fused prep + 33.5M-pair distance kernel ----------------
// grid (SS, 2, BB), 128 threads; thread t handles m = t + (4h+2g+half)*128.
__global__ void __launch_bounds__(128, 7) k_main(const float* __restrict__ pred_r,
                                                 const float* __restrict__ pred_t,
                                                 const float* __restrict__ pred_c,
                                                 const float* __restrict__ points,
                                                 const float* __restrict__ mp,
                                                 const float* __restrict__ tg) {
    const int s = blockIdx.x;
    const int h = blockIdx.y;
    const int b = blockIdx.z;
    const int t = threadIdx.x;

    __shared__ u64 sm[TN][6];   // [n][j], splatted (v,v): mp.x,y,z, tg.x,y,z  (48B rows)
    __shared__ float sv[128];
    __shared__ int   si[128];

    // ---- n-tile load (splatted) ----
    if (t < TN) {
        int n = s * TN + t;
        const float* mpr = mp + ((size_t)b * NN + n) * 3;
        const float* tgr = tg + ((size_t)b * NN + n) * 3;
        float a0 = mpr[0], a1 = mpr[1], a2 = mpr[2];
        float c0 = tgr[0], c1 = tgr[1], c2 = tgr[2];
        sm[t][0] = pack2(a0, a0);
        sm[t][1] = pack2(a1, a1);
        sm[t][2] = pack2(a2, a2);
        sm[t][3] = pack2(c0, c0);
        sm[t][4] = pack2(c1, c1);
        sm[t][5] = pack2(c2, c2);
    }

    // ---- inline prep: R/t for this thread's 4 m's, packed as f32x2 pairs ----
    u64 C[2][12];
    float cmax = -1e30f; int cidx = 0;
    #pragma unroll
    for (int g = 0; g < 2; g++) {
        float Rl[12], Rh[12];
        #pragma unroll
        for (int half = 0; half < 2; half++) {
            int m = t + (4 * h + 2 * g + half) * 128;
            int i = b * MM + m;
            float4 q = reinterpret_cast<const float4*>(pred_r)[i];
            float t0 = points[3 * i + 0] + pred_t[3 * i + 0];
            float t1 = points[3 * i + 1] + pred_t[3 * i + 1];
            float t2 = points[3 * i + 2] + pred_t[3 * i + 2];
            quat_to_Rt(q.x, q.y, q.z, q.w, t0, t1, t2, half ? Rh : Rl);
            float c = fmaxf(pred_c[i], 1e-6f);
            if (s == 0) g_c[i] = c;
            if (c > cmax) { cmax = c; cidx = m; }   // increasing m order -> first-max tie-break
        }
        #pragma unroll
        for (int j = 0; j < 12; j++) C[g][j] = pack2(Rl[j], Rh[j]);
    }

    // ---- block argmax partial over this block's 512 m's (result used only by s==0) ----
    sv[t] = cmax; si[t] = cidx;
    __syncthreads();                // also covers the sm tile
    #pragma unroll
    for (int off = 64; off > 0; off >>= 1) {
        if (t < off) {
            if (sv[t + off] > sv[t] || (sv[t + off] == sv[t] && si[t + off] < si[t])) {
                sv[t] = sv[t + off]; si[t] = si[t + off];
            }
        }
        __syncthreads();
    }
    if (s == 0 && t == 0) { g_amaxv[b * 2 + h] = sv[0]; g_amaxi[b * 2 + h] = si[0]; }

    // ---- main loop ----
    float acc[4];
    #pragma unroll
    for (int a = 0; a < 4; a++) acc[a] = 0.0f;

    const u64 NEG1 = 0xBF800000BF800000ULL;

    #pragma unroll 4
    for (int n = 0; n < TN; n++) {
        ulonglong2 p01 = *reinterpret_cast<const ulonglong2*>(&sm[n][0]);
        ulonglong2 p23 = *reinterpret_cast<const ulonglong2*>(&sm[n][2]);
        ulonglong2 p45 = *reinterpret_cast<const ulonglong2*>(&sm[n][4]);
        u64 m0 = p01.x, m1 = p01.y, m2 = p23.x;
        u64 v0 = p23.y, v1 = p45.x, v2 = p45.y;
        #pragma unroll
        for (int g = 0; g < 2; g++) {
            u64 s0 = fma2(v0, NEG1, C[g][9]);
            u64 s1 = fma2(v1, NEG1, C[g][10]);
            u64 s2 = fma2(v2, NEG1, C[g][11]);
            u64 d0 = fma2(m0, C[g][0], fma2(m1, C[g][3], fma2(m2, C[g][6], s0)));
            u64 d1 = fma2(m0, C[g][1], fma2(m1, C[g][4], fma2(m2, C[g][7], s1)));
            u64 d2 = fma2(m0, C[g][2], fma2(m1, C[g][5], fma2(m2, C[g][8], s2)));
            u64 sq = fma2(d0, d0, fma2(d1, d1, mul2(d2, d2)));
            float sa, sb; unpack2(sq, sa, sb);
            acc[2 * g]     += sqrt_approx(sa);
            acc[2 * g + 1] += sqrt_approx(sb);
        }
    }

    #pragma unroll
    for (int g = 0; g < 2; g++) {
        int m0i = t + (4 * h + 2 * g) * 128;
        g_part[s][(size_t)b * MM + m0i]       = acc[2 * g];
        g_part[s][(size_t)b * MM + m0i + 128] = acc[2 * g + 1];
    }
}

// ---------------- K2: combine partials + loss partials + argmax finish + R_best ----------------
__global__ void k_combine(const float* __restrict__ wptr,
                          const float* __restrict__ pred_r,
                          const float* __restrict__ pred_t,
                          const float* __restrict__ points) {
    if (blockIdx.x == 256) {
        int t = threadIdx.x;
        if (t < BB) {
            float v0 = g_amaxv[t * 2 + 0], v1 = g_amaxv[t * 2 + 1];
            int   i0 = g_amaxi[t * 2 + 0], i1 = g_amaxi[t * 2 + 1];
            int which = (v1 > v0) ? i1 : i0;   // tie -> h=0 (smaller m)
            g_which[t] = which;
            int i = t * MM + which;
            float4 q = reinterpret_cast<const float4*>(pred_r)[i];
            float t0 = points[3 * i + 0] + pred_t[3 * i + 0];
            float t1 = points[3 * i + 1] + pred_t[3 * i + 1];
            float t2 = points[3 * i + 2] + pred_t[3 * i + 2];
            float o[12];
            quat_to_Rt(q.x, q.y, q.z, q.w, t0, t1, t2, o);
            #pragma unroll
            for (int j = 0; j < 12; j++) g_Rbest[t][j] = o[j];
        }
        return;
    }
    int i = blockIdx.x * 128 + threadIdx.x;  // 256 blocks x 128 = 32768
    float w = *wptr;
    float dsum = 0.0f;
    #pragma unroll
    for (int ss = 0; ss < SS; ss++) dsum += g_part[ss][i];
    g_dish[i] = dsum;
    float c = g_c[i];
    float term = dsum * (1.0f / (float)NN) * c - w * __logf(c);

    __shared__ float sbuf[128];
    int t = threadIdx.x;
    sbuf[t] = term;
    __syncthreads();
    #pragma unroll
    for (int off = 64; off > 0; off >>= 1) {
        if (t < off) sbuf[t] += sbuf[t + off];
        __syncthreads();
    }
    if (t == 0) g_lpart[blockIdx.x] = sbuf[0];
}

// ---------------- K3: transform new_points / new_target + final scalars ----------------
__global__ void k_transform(const float* __restrict__ points,
                            const float* __restrict__ target,
                            float* __restrict__ out) {
    if (blockIdx.x == 256) {
        int t = threadIdx.x;   // 256 threads
        __shared__ float sbuf[256];
        __shared__ float sdb;
        sbuf[t] = g_lpart[t];
        if (t < 32) {
            float db = g_dish[t * MM + g_which[t]];
            #pragma unroll
            for (int off = 16; off > 0; off >>= 1)
                db += __shfl_down_sync(0xffffffffu, db, off);
            if (t == 0) sdb = db;
        }
        __syncthreads();
        #pragma unroll
        for (int off = 128; off > 0; off >>= 1) {
            if (t < off) sbuf[t] += sbuf[t + off];
            __syncthreads();
        }
        if (t == 0) {
            out[0] = sbuf[0] / (float)(BB * MM);
            out[1] = sdb * (1.0f / (float)NN) / (float)BB;
        }
        return;
    }
    int id = blockIdx.x * 256 + threadIdx.x; // 256 blocks x 256 = 65536 = BB*(MM+NN)
    int b = id >> 11;
    int r = id & 2047;

    float Rb[12];
    #pragma unroll
    for (int j = 0; j < 12; j++) Rb[j] = g_Rbest[b][j];

    const float* src;
    float* dst;
    if (r < MM) {
        src = points + ((size_t)b * MM + r) * 3;
        dst = out + 2 + ((size_t)b * MM + r) * 3;
    } else {
        int n = r - MM;
        src = target + ((size_t)b * NN + n) * 3;
        dst = out + 2 + (size_t)BB * MM * 3 + ((size_t)b * NN + n) * 3;
    }
    float d0 = src[0] - Rb[9];
    float d1 = src[1] - Rb[10];
    float d2 = src[2] - Rb[11];
    #pragma unroll
    for (int j = 0; j < 3; j++)
        dst[j] = d0 * Rb[0 * 3 + j] + d1 * Rb[1 * 3 + j] + d2 * Rb[2 * 3 + j];
}

// ---------------- launch ----------------
extern "C" void kernel_launch(void* const* d_in, const int* in_sizes, int n_in,
                              void* d_out, int out_size) {
    const float* pred_r       = (const float*)d_in[0];
    const float* pred_t       = (const float*)d_in[1];
    const float* pred_c       = (const float*)d_in[2];
    const float* target       = (const float*)d_in[3];
    const float* model_points = (const float*)d_in[4];
    // d_in[5] = idx (unused, refine path)
    const float* points       = (const float*)d_in[6];
    const float* wptr         = (const float*)d_in[7];
    // d_in[8] = refine (unused)
    float* out = (float*)d_out;

    k_main<<<dim3(SS, 2, BB), 128>>>(pred_r, pred_t, pred_c, points, model_points, target);
    k_combine<<<257, 128>>>(wptr, pred_r, pred_t, points);
    k_transform<<<257, 256>>>(points, target, out);
}